// round 15
// baseline (speedup 1.0000x reference)
#include <cuda_runtime.h>
#include <cuda_fp16.h>
#include <cstdint>

// out[b,n,m] = sum_e A[b,n,e]*B[b,m,e];  b=8, n=m=2048, e=1024, fp32.
// R14: PROBE fp16-accumulator HMMA rate. Same structure as R13 except the
//      per-chunk MMA body: each (mi,ni) fragment runs a 2-step fp16-acc chain
//      (k=32) then promotes into persistent fp32 accumulators.
//      If legacy f16-acc HMMA is 2x rate -> GEMM ~170us. Else revert.

#define NB 8
#define NN 2048
#define MM 2048
#define EE 1024

#define TILE 128
#define KC 32              // fp16 k per chunk = one fp16-acc chain
#define NCHUNKS (EE / KC)  // 32
#define NSTAGE 2

#define ROWSTRIDE 80       // 64B data + 16B pad; conflict-free ldmatrix
#define TILE_BYTES (128 * ROWSTRIDE)         // 10240
#define OFF_AH 0
#define OFF_BH (1 * TILE_BYTES)
#define STAGE_BYTES (2 * TILE_BYTES)         // 20480
#define SMEM_TOTAL (NSTAGE * STAGE_BYTES)    // 40960

#define ELEMS (NB * NN * EE)
__device__ __half g_Ah[ELEMS];
__device__ __half g_Bh[ELEMS];

__device__ __forceinline__ uint32_t smem_u32(const void* p) {
    uint32_t a;
    asm("{ .reg .u64 t; cvta.to.shared.u64 t, %1; cvt.u32.u64 %0, t; }" : "=r"(a) : "l"(p));
    return a;
}
__device__ __forceinline__ void cp16cg(uint32_t dst, const void* src) {
    asm volatile("cp.async.cg.shared.global [%0], [%1], 16;" :: "r"(dst), "l"(src));
}
__device__ __forceinline__ void ldm_x4(uint32_t* d, uint32_t addr) {
    asm volatile("ldmatrix.sync.aligned.m8n8.x4.shared.b16 {%0,%1,%2,%3}, [%4];"
                 : "=r"(d[0]), "=r"(d[1]), "=r"(d[2]), "=r"(d[3]) : "r"(addr));
}
// fp16-accumulator mma: D(f16 2regs) = A*B + C(f16 2regs)
__device__ __forceinline__ void mma16816_f16(uint32_t& d0, uint32_t& d1,
                                             const uint32_t* a, uint32_t b0, uint32_t b1,
                                             uint32_t c0, uint32_t c1) {
    asm volatile(
        "mma.sync.aligned.m16n8k16.row.col.f16.f16.f16.f16 "
        "{%0,%1}, {%2,%3,%4,%5}, {%6,%7}, {%8,%9};"
        : "=r"(d0), "=r"(d1)
        : "r"(a[0]), "r"(a[1]), "r"(a[2]), "r"(a[3]), "r"(b0), "r"(b1),
          "r"(c0), "r"(c1));
}

// ---- fused convert: A,B fp32 -> fp16 ----
__global__ __launch_bounds__(256)
void convert_fused_kernel(const float* __restrict__ A, const float* __restrict__ B) {
    size_t i = (size_t)blockIdx.x * blockDim.x + threadIdx.x;
    const size_t quads = ELEMS / 4;
    if (i >= 2 * quads) return;
    const float* src = (i < quads) ? A : B;
    __half* dst = (i < quads) ? g_Ah : g_Bh;
    size_t j = (i < quads) ? i : i - quads;
    float4 v = ((const float4*)src)[j];
    ((__half2*)dst)[2 * j]     = __half2{__float2half_rn(v.x), __float2half_rn(v.y)};
    ((__half2*)dst)[2 * j + 1] = __half2{__float2half_rn(v.z), __float2half_rn(v.w)};
}

__global__ __launch_bounds__(256, 2)
void bgemm_mma_kernel(float* __restrict__ C) {
    extern __shared__ char smem[];
    const uint32_t sb = smem_u32(smem);
    const int tid = threadIdx.x;
    const int lane = tid & 31;
    const int wid = tid >> 5;
    const int wm = wid >> 2;   // 0..1  -> 64-row slab (n)
    const int wn = wid & 3;    // 0..3  -> 32-col slab (m)

    const int bz = blockIdx.z;
    const int n0 = blockIdx.y * TILE;
    const int m0 = blockIdx.x * TILE;

    const __half* gAh = g_Ah + ((size_t)bz * NN + n0) * EE;
    const __half* gBh = g_Bh + ((size_t)bz * MM + m0) * EE;

    auto load_stage = [&](int kc, int st) {
        const uint32_t base = sb + st * STAGE_BYTES;
        const int e0 = kc * KC;
        const int row = tid >> 1;
        const int q2 = (tid & 1) * 2;
#pragma unroll
        for (int q = q2; q < q2 + 2; q++) {
            const uint32_t off = (uint32_t)(row * ROWSTRIDE + q * 16);
            const size_t gs = (size_t)row * EE + e0 + q * 8;
            cp16cg(base + OFF_AH + off, gAh + gs);
            cp16cg(base + OFF_BH + off, gBh + gs);
        }
    };

    float acc[4][4][4];
#pragma unroll
    for (int mi = 0; mi < 4; mi++)
#pragma unroll
        for (int ni = 0; ni < 4; ni++)
#pragma unroll
            for (int q = 0; q < 4; q++) acc[mi][ni][q] = 0.0f;

    load_stage(0, 0);
    asm volatile("cp.async.commit_group;" ::: "memory");

    const int xrow = (lane & 7) + ((lane >> 3) & 1) * 8;  // 0..15
    const uint32_t kb = ((lane >> 4) & 1) * 16;           // k8..15 byte sel

    const uint32_t aRowOff = (uint32_t)((wm * 64 + xrow) * ROWSTRIDE) + kb;
    const uint32_t bRowOff = (uint32_t)((wn * 32 + xrow) * ROWSTRIDE) + kb;

    for (int i = 0; i < NCHUNKS; i++) {
        asm volatile("cp.async.wait_group 0;" ::: "memory");
        __syncthreads();
        if (i + 1 < NCHUNKS) {
            load_stage(i + 1, (i + 1) & 1);
            asm volatile("cp.async.commit_group;" ::: "memory");
        }

        const uint32_t stb = sb + (i & 1) * STAGE_BYTES;
        const uint32_t aR = stb + aRowOff;
        const uint32_t bR = stb + bRowOff;

        // B fragments for BOTH k16 steps of this chunk (16 regs)
        uint32_t Bx[2][2][4];
#pragma unroll
        for (int s = 0; s < 2; s++)
#pragma unroll
            for (int nj = 0; nj < 2; nj++)
                ldm_x4(Bx[s][nj],
                       OFF_BH + bR + (uint32_t)(nj * 16 * ROWSTRIDE) + (uint32_t)s * 32);

        // process mi in two halves so only 16 A-frag regs are live
#pragma unroll
        for (int h = 0; h < 2; h++) {
            uint32_t Ax[2][2][4];
#pragma unroll
            for (int s = 0; s < 2; s++)
#pragma unroll
                for (int m2 = 0; m2 < 2; m2++)
                    ldm_x4(Ax[s][m2],
                           OFF_AH + aR + (uint32_t)((h * 2 + m2) * 16 * ROWSTRIDE) + (uint32_t)s * 32);

#pragma unroll
            for (int m2 = 0; m2 < 2; m2++)
#pragma unroll
                for (int ni = 0; ni < 4; ni++) {
                    const int nj = ni >> 1, w = ni & 1;
                    uint32_t d0, d1;
                    // 2-step fp16-acc chain (k=32), then promote to f32
                    mma16816_f16(d0, d1, Ax[0][m2], Bx[0][nj][w], Bx[0][nj][w + 2], 0u, 0u);
                    mma16816_f16(d0, d1, Ax[1][m2], Bx[1][nj][w], Bx[1][nj][w + 2], d0, d1);
                    float* a4 = acc[h * 2 + m2][ni];
                    float2 f0 = __half22float2(*reinterpret_cast<__half2*>(&d0));
                    float2 f1 = __half22float2(*reinterpret_cast<__half2*>(&d1));
                    a4[0] += f0.x; a4[1] += f0.y;
                    a4[2] += f1.x; a4[3] += f1.y;
                }
        }
    }

    float* Cb = C + ((size_t)bz * NN + n0 + wm * 64) * MM + m0 + wn * 32;
    const int r = lane >> 2, cc = (lane & 3) * 2;
#pragma unroll
    for (int mi = 0; mi < 4; mi++)
#pragma unroll
        for (int ni = 0; ni < 4; ni++) {
            float* p0 = Cb + (size_t)(mi * 16 + r) * MM + ni * 8 + cc;
            float* p1 = p0 + 8 * MM;
            *(float2*)p0 = make_float2(acc[mi][ni][0], acc[mi][ni][1]);
            *(float2*)p1 = make_float2(acc[mi][ni][2], acc[mi][ni][3]);
        }
}

extern "C" void kernel_launch(void* const* d_in, const int* in_sizes, int n_in,
                              void* d_out, int out_size) {
    const float* A = (const float*)d_in[0];
    const float* B = (const float*)d_in[1];
    float* C = (float*)d_out;

    const int cvt_blocks = (2 * (ELEMS / 4) + 255) / 256;
    convert_fused_kernel<<<cvt_blocks, 256>>>(A, B);

    cudaFuncSetAttribute(bgemm_mma_kernel, cudaFuncAttributeMaxDynamicSharedMemorySize, SMEM_TOTAL);
    dim3 grid(MM / TILE, NN / TILE, NB);
    bgemm_mma_kernel<<<grid, 256, SMEM_TOTAL>>>(C);
}

// round 16
// speedup vs baseline: 1.0735x; 1.0735x over previous
#include <cuda_runtime.h>
#include <cuda_fp16.h>
#include <cstdint>

// out[b,n,m] = sum_e A[b,n,e]*B[b,m,e];  b=8, n=m=2048, e=1024, fp32.
// R15: single-pass fp16 mma.sync (f32 acc) — R13 body + 3-stage cp.async
//      pipeline with wait_group 1 (deeper latency hiding, softer wait).
//      Config: 128x128 CTA tile, 8 warps x (64x32), KC=32, 3 stages, 2 CTAs/SM.

#define NB 8
#define NN 2048
#define MM 2048
#define EE 1024

#define TILE 128
#define KC 32              // fp16 k per chunk
#define NCHUNKS (EE / KC)  // 32
#define NSTAGE 3

#define ROWSTRIDE 80       // 64B data + 16B pad; conflict-free ldmatrix
#define TILE_BYTES (128 * ROWSTRIDE)         // 10240
#define OFF_AH 0
#define OFF_BH (1 * TILE_BYTES)
#define STAGE_BYTES (2 * TILE_BYTES)         // 20480
#define SMEM_TOTAL (NSTAGE * STAGE_BYTES)    // 61440

#define ELEMS (NB * NN * EE)
__device__ __half g_Ah[ELEMS];
__device__ __half g_Bh[ELEMS];

__device__ __forceinline__ uint32_t smem_u32(const void* p) {
    uint32_t a;
    asm("{ .reg .u64 t; cvta.to.shared.u64 t, %1; cvt.u32.u64 %0, t; }" : "=r"(a) : "l"(p));
    return a;
}
__device__ __forceinline__ void cp16cg(uint32_t dst, const void* src) {
    asm volatile("cp.async.cg.shared.global [%0], [%1], 16;" :: "r"(dst), "l"(src));
}
__device__ __forceinline__ void ldm_x4(uint32_t* d, uint32_t addr) {
    asm volatile("ldmatrix.sync.aligned.m8n8.x4.shared.b16 {%0,%1,%2,%3}, [%4];"
                 : "=r"(d[0]), "=r"(d[1]), "=r"(d[2]), "=r"(d[3]) : "r"(addr));
}
__device__ __forceinline__ void mma16816(float* d, const uint32_t* a, uint32_t b0, uint32_t b1) {
    asm volatile(
        "mma.sync.aligned.m16n8k16.row.col.f32.f16.f16.f32 "
        "{%0,%1,%2,%3}, {%4,%5,%6,%7}, {%8,%9}, {%0,%1,%2,%3};"
        : "+f"(d[0]), "+f"(d[1]), "+f"(d[2]), "+f"(d[3])
        : "r"(a[0]), "r"(a[1]), "r"(a[2]), "r"(a[3]), "r"(b0), "r"(b1));
}

// ---- fused convert: A,B fp32 -> fp16 ----
__global__ __launch_bounds__(256)
void convert_fused_kernel(const float* __restrict__ A, const float* __restrict__ B) {
    size_t i = (size_t)blockIdx.x * blockDim.x + threadIdx.x;
    const size_t quads = ELEMS / 4;
    if (i >= 2 * quads) return;
    const float* src = (i < quads) ? A : B;
    __half* dst = (i < quads) ? g_Ah : g_Bh;
    size_t j = (i < quads) ? i : i - quads;
    float4 v = ((const float4*)src)[j];
    ((__half2*)dst)[2 * j]     = __half2{__float2half_rn(v.x), __float2half_rn(v.y)};
    ((__half2*)dst)[2 * j + 1] = __half2{__float2half_rn(v.z), __float2half_rn(v.w)};
}

__global__ __launch_bounds__(256, 2)
void bgemm_mma_kernel(float* __restrict__ C) {
    extern __shared__ char smem[];
    const uint32_t sb = smem_u32(smem);
    const int tid = threadIdx.x;
    const int lane = tid & 31;
    const int wid = tid >> 5;
    const int wm = wid >> 2;   // 0..1  -> 64-row slab (n)
    const int wn = wid & 3;    // 0..3  -> 32-col slab (m)

    const int bz = blockIdx.z;
    const int n0 = blockIdx.y * TILE;
    const int m0 = blockIdx.x * TILE;

    const __half* gAh = g_Ah + ((size_t)bz * NN + n0) * EE;
    const __half* gBh = g_Bh + ((size_t)bz * MM + m0) * EE;

    // per stage: 2 tiles x 128 rows x 4x16B; each thread: row=tid>>1, 2 quads
    auto load_stage = [&](int kc, int st) {
        const uint32_t base = sb + st * STAGE_BYTES;
        const int e0 = kc * KC;
        const int row = tid >> 1;
        const int q2 = (tid & 1) * 2;
#pragma unroll
        for (int q = q2; q < q2 + 2; q++) {
            const uint32_t off = (uint32_t)(row * ROWSTRIDE + q * 16);
            const size_t gs = (size_t)row * EE + e0 + q * 8;
            cp16cg(base + OFF_AH + off, gAh + gs);
            cp16cg(base + OFF_BH + off, gBh + gs);
        }
    };

    float acc[4][4][4];
#pragma unroll
    for (int mi = 0; mi < 4; mi++)
#pragma unroll
        for (int ni = 0; ni < 4; ni++)
#pragma unroll
            for (int q = 0; q < 4; q++) acc[mi][ni][q] = 0.0f;

    // prologue: 2 stages in flight
    load_stage(0, 0);
    asm volatile("cp.async.commit_group;" ::: "memory");
    load_stage(1, 1);
    asm volatile("cp.async.commit_group;" ::: "memory");

    const int xrow = (lane & 7) + ((lane >> 3) & 1) * 8;  // 0..15
    const uint32_t kb = ((lane >> 4) & 1) * 16;           // k8..15 byte sel

    const uint32_t aRowOff = (uint32_t)((wm * 64 + xrow) * ROWSTRIDE) + kb;
    const uint32_t bRowOff = (uint32_t)((wn * 32 + xrow) * ROWSTRIDE) + kb;

    int st = 0;  // stage index = i % 3, tracked incrementally
    for (int i = 0; i < NCHUNKS; i++) {
        // allow 1 newer group to remain in flight; only the oldest must land
        asm volatile("cp.async.wait_group 1;" ::: "memory");
        __syncthreads();
        if (i + 2 < NCHUNKS) {
            int st2 = st + 2; if (st2 >= NSTAGE) st2 -= NSTAGE;
            load_stage(i + 2, st2);
            asm volatile("cp.async.commit_group;" ::: "memory");
        }

        const uint32_t stb = sb + (uint32_t)st * STAGE_BYTES;
        const uint32_t aR = stb + aRowOff;
        const uint32_t bR = stb + bRowOff;

#pragma unroll
        for (int kk = 0; kk < 2; kk++) {
            const uint32_t ko = (uint32_t)kk * 32;  // 16 fp16 = 32B per k16
            uint32_t Ax[4][4], Bx[2][4];
#pragma unroll
            for (int mi = 0; mi < 4; mi++)
                ldm_x4(Ax[mi], OFF_AH + aR + (uint32_t)(mi * 16 * ROWSTRIDE) + ko);
#pragma unroll
            for (int nj = 0; nj < 2; nj++)
                ldm_x4(Bx[nj], OFF_BH + bR + (uint32_t)(nj * 16 * ROWSTRIDE) + ko);
#pragma unroll
            for (int mi = 0; mi < 4; mi++)
#pragma unroll
                for (int ni = 0; ni < 4; ni++) {
                    int nj = ni >> 1, w = ni & 1;
                    mma16816(acc[mi][ni], Ax[mi], Bx[nj][w], Bx[nj][w + 2]);
                }
        }

        if (++st == NSTAGE) st = 0;
    }

    float* Cb = C + ((size_t)bz * NN + n0 + wm * 64) * MM + m0 + wn * 32;
    const int r = lane >> 2, cc = (lane & 3) * 2;
#pragma unroll
    for (int mi = 0; mi < 4; mi++)
#pragma unroll
        for (int ni = 0; ni < 4; ni++) {
            float* p0 = Cb + (size_t)(mi * 16 + r) * MM + ni * 8 + cc;
            float* p1 = p0 + 8 * MM;
            *(float2*)p0 = make_float2(acc[mi][ni][0], acc[mi][ni][1]);
            *(float2*)p1 = make_float2(acc[mi][ni][2], acc[mi][ni][3]);
        }
}

extern "C" void kernel_launch(void* const* d_in, const int* in_sizes, int n_in,
                              void* d_out, int out_size) {
    const float* A = (const float*)d_in[0];
    const float* B = (const float*)d_in[1];
    float* C = (float*)d_out;

    const int cvt_blocks = (2 * (ELEMS / 4) + 255) / 256;
    convert_fused_kernel<<<cvt_blocks, 256>>>(A, B);

    cudaFuncSetAttribute(bgemm_mma_kernel, cudaFuncAttributeMaxDynamicSharedMemorySize, SMEM_TOTAL);
    dim3 grid(MM / TILE, NN / TILE, NB);
    bgemm_mma_kernel<<<grid, 256, SMEM_TOTAL>>>(C);
}

// round 17
// speedup vs baseline: 1.1090x; 1.0331x over previous
#include <cuda_runtime.h>
#include <cuda_fp16.h>
#include <cstdint>

// out[b,n,m] = sum_e A[b,n,e]*B[b,m,e];  b=8, n=m=2048, e=1024, fp32.
// R16: fused convert+GEMM, one launch. CTAs 0..255 convert fp32->fp16
//      batch-by-batch and release per-batch flags; CTAs 256.. run the R13
//      single-pass fp16 mma.sync GEMM, spinning (acquire) on their batch flag.
//      Zero-flags pre-kernel keeps every call's work identical.

#define NB 8
#define NN 2048
#define MM 2048
#define EE 1024

#define TILE 128
#define KC 32              // fp16 k per chunk
#define NCHUNKS (EE / KC)  // 32
#define NSTAGE 2

#define ROWSTRIDE 80       // 64B data + 16B pad; conflict-free ldmatrix
#define TILE_BYTES (128 * ROWSTRIDE)         // 10240
#define OFF_AH 0
#define OFF_BH (1 * TILE_BYTES)
#define STAGE_BYTES (2 * TILE_BYTES)         // 20480
#define SMEM_TOTAL (NSTAGE * STAGE_BYTES)    // 40960

#define CONV_CTAS 256
#define GEMM_CTAS (NB * (NN / TILE) * (MM / TILE))   // 2048
#define TOTAL_CTAS (CONV_CTAS + GEMM_CTAS)           // 2304

#define ELEMS (NB * NN * EE)
#define QUADS_PER_BATCH (NN * EE / 4)                // 524288 float4 per matrix per batch
__device__ __half g_Ah[ELEMS];
__device__ __half g_Bh[ELEMS];
__device__ int g_done[NB];

__device__ __forceinline__ uint32_t smem_u32(const void* p) {
    uint32_t a;
    asm("{ .reg .u64 t; cvta.to.shared.u64 t, %1; cvt.u32.u64 %0, t; }" : "=r"(a) : "l"(p));
    return a;
}
__device__ __forceinline__ void cp16cg(uint32_t dst, const void* src) {
    asm volatile("cp.async.cg.shared.global [%0], [%1], 16;" :: "r"(dst), "l"(src));
}
__device__ __forceinline__ void ldm_x4(uint32_t* d, uint32_t addr) {
    asm volatile("ldmatrix.sync.aligned.m8n8.x4.shared.b16 {%0,%1,%2,%3}, [%4];"
                 : "=r"(d[0]), "=r"(d[1]), "=r"(d[2]), "=r"(d[3]) : "r"(addr));
}
__device__ __forceinline__ void mma16816(float* d, const uint32_t* a, uint32_t b0, uint32_t b1) {
    asm volatile(
        "mma.sync.aligned.m16n8k16.row.col.f32.f16.f16.f32 "
        "{%0,%1,%2,%3}, {%4,%5,%6,%7}, {%8,%9}, {%0,%1,%2,%3};"
        : "+f"(d[0]), "+f"(d[1]), "+f"(d[2]), "+f"(d[3])
        : "r"(a[0]), "r"(a[1]), "r"(a[2]), "r"(a[3]), "r"(b0), "r"(b1));
}

__global__ void zero_flags_kernel() {
    if (threadIdx.x < NB) g_done[threadIdx.x] = 0;
}

__device__ __forceinline__ void cvt_quad(const float4* src, __half2* dst, size_t q) {
    float4 v = src[q];
    dst[2 * q]     = __half2{__float2half_rn(v.x), __float2half_rn(v.y)};
    dst[2 * q + 1] = __half2{__float2half_rn(v.z), __float2half_rn(v.w)};
}

__global__ __launch_bounds__(256, 2)
void fused_kernel(const float* __restrict__ Af, const float* __restrict__ Bf,
                  float* __restrict__ C) {
    extern __shared__ char smem[];
    const int tid = threadIdx.x;

    if (blockIdx.x < CONV_CTAS) {
        // ---------------- convert role: batches in order, flag per batch ----
        const size_t gtid = (size_t)blockIdx.x * 256 + tid;   // 0..65535
        const float4* As4 = (const float4*)Af;
        const float4* Bs4 = (const float4*)Bf;
        __half2* Ad2 = (__half2*)g_Ah;
        __half2* Bd2 = (__half2*)g_Bh;
        for (int z = 0; z < NB; z++) {
            const size_t base = (size_t)z * QUADS_PER_BATCH;
#pragma unroll
            for (int r = 0; r < QUADS_PER_BATCH / 65536; r++) {   // 8 iters
                const size_t q = base + gtid + (size_t)r * 65536;
                cvt_quad(As4, Ad2, q);
                cvt_quad(Bs4, Bd2, q);
            }
            __threadfence();
            __syncthreads();
            if (tid == 0) atomicAdd(&g_done[z], 1);
        }
        return;
    }

    // ---------------- GEMM role (R13 body) ------------------------------
    const int id = blockIdx.x - CONV_CTAS;      // 0..2047, batch-major
    const int bz = id >> 8;                      // 8 batches x 256 tiles
    const int tl = id & 255;
    const int m0 = (tl & 15) * TILE;
    const int n0 = ((tl >> 4) & 15) * TILE;

    // wait until this batch's conversion is complete
    if (tid == 0) {
        int v;
        do {
            asm volatile("ld.acquire.gpu.global.s32 %0, [%1];"
                         : "=r"(v) : "l"(&g_done[bz]) : "memory");
        } while (v < CONV_CTAS);
    }
    __syncthreads();

    const uint32_t sb = smem_u32(smem);
    const int lane = tid & 31;
    const int wid = tid >> 5;
    const int wm = wid >> 2;   // 0..1  -> 64-row slab (n)
    const int wn = wid & 3;    // 0..3  -> 32-col slab (m)

    const __half* gAh = g_Ah + ((size_t)bz * NN + n0) * EE;
    const __half* gBh = g_Bh + ((size_t)bz * MM + m0) * EE;

    auto load_stage = [&](int kc, int st) {
        const uint32_t base = sb + st * STAGE_BYTES;
        const int e0 = kc * KC;
        const int row = tid >> 1;
        const int q2 = (tid & 1) * 2;
#pragma unroll
        for (int q = q2; q < q2 + 2; q++) {
            const uint32_t off = (uint32_t)(row * ROWSTRIDE + q * 16);
            const size_t gs = (size_t)row * EE + e0 + q * 8;
            cp16cg(base + OFF_AH + off, gAh + gs);
            cp16cg(base + OFF_BH + off, gBh + gs);
        }
    };

    float acc[4][4][4];
#pragma unroll
    for (int mi = 0; mi < 4; mi++)
#pragma unroll
        for (int ni = 0; ni < 4; ni++)
#pragma unroll
            for (int q = 0; q < 4; q++) acc[mi][ni][q] = 0.0f;

    load_stage(0, 0);
    asm volatile("cp.async.commit_group;" ::: "memory");

    const int xrow = (lane & 7) + ((lane >> 3) & 1) * 8;  // 0..15
    const uint32_t kb = ((lane >> 4) & 1) * 16;           // k8..15 byte sel

    const uint32_t aRowOff = (uint32_t)((wm * 64 + xrow) * ROWSTRIDE) + kb;
    const uint32_t bRowOff = (uint32_t)((wn * 32 + xrow) * ROWSTRIDE) + kb;

    for (int i = 0; i < NCHUNKS; i++) {
        asm volatile("cp.async.wait_group 0;" ::: "memory");
        __syncthreads();
        if (i + 1 < NCHUNKS) {
            load_stage(i + 1, (i + 1) & 1);
            asm volatile("cp.async.commit_group;" ::: "memory");
        }

        const uint32_t stb = sb + (i & 1) * STAGE_BYTES;
        const uint32_t aR = stb + aRowOff;
        const uint32_t bR = stb + bRowOff;

#pragma unroll
        for (int kk = 0; kk < 2; kk++) {
            const uint32_t ko = (uint32_t)kk * 32;  // 16 fp16 = 32B per k16
            uint32_t Ax[4][4], Bx[2][4];
#pragma unroll
            for (int mi = 0; mi < 4; mi++)
                ldm_x4(Ax[mi], OFF_AH + aR + (uint32_t)(mi * 16 * ROWSTRIDE) + ko);
#pragma unroll
            for (int nj = 0; nj < 2; nj++)
                ldm_x4(Bx[nj], OFF_BH + bR + (uint32_t)(nj * 16 * ROWSTRIDE) + ko);
#pragma unroll
            for (int mi = 0; mi < 4; mi++)
#pragma unroll
                for (int ni = 0; ni < 4; ni++) {
                    int nj = ni >> 1, w = ni & 1;
                    mma16816(acc[mi][ni], Ax[mi], Bx[nj][w], Bx[nj][w + 2]);
                }
        }
    }

    float* Cb = C + ((size_t)bz * NN + n0 + wm * 64) * MM + m0 + wn * 32;
    const int r = lane >> 2, cc = (lane & 3) * 2;
#pragma unroll
    for (int mi = 0; mi < 4; mi++)
#pragma unroll
        for (int ni = 0; ni < 4; ni++) {
            float* p0 = Cb + (size_t)(mi * 16 + r) * MM + ni * 8 + cc;
            float* p1 = p0 + 8 * MM;
            *(float2*)p0 = make_float2(acc[mi][ni][0], acc[mi][ni][1]);
            *(float2*)p1 = make_float2(acc[mi][ni][2], acc[mi][ni][3]);
        }
}

extern "C" void kernel_launch(void* const* d_in, const int* in_sizes, int n_in,
                              void* d_out, int out_size) {
    const float* A = (const float*)d_in[0];
    const float* B = (const float*)d_in[1];
    float* C = (float*)d_out;

    zero_flags_kernel<<<1, 32>>>();

    cudaFuncSetAttribute(fused_kernel, cudaFuncAttributeMaxDynamicSharedMemorySize, SMEM_TOTAL);
    fused_kernel<<<TOTAL_CTAS, 256, SMEM_TOTAL>>>(A, B, C);
}